// round 10
// baseline (speedup 1.0000x reference)
#include <cuda_runtime.h>
#include <cuda_bf16.h>
#include <cstdint>

#define N_ATOMS 50000
#define N_EDGES 1600000
#define NF      128
#define NRBF    20
#define TSTRIDE 130
#define NTILES  (N_EDGES / 128)   // 12500
#define GRID_EDGE 296             // 2 CTAs x 148 SMs, persistent

// B (W2^T) bf16 tile row stride in elements (128 data + 8 pad -> 272B rows)
#define KSTR 136
#define BTILE_BYTES (128 * KSTR * 2)   // 34816
// W1^T / f tile row stride: 40 bf16 = 80B (banks stride 20 -> conflict-free ldsm)
#define W1STR 40
#define W1TILE_BYTES (128 * W1STR * 2) // 10240

// ---------------- device globals (no allocation allowed) -------------------
__device__ float g_h[(size_t)N_ATOMS * NF];
__device__ float g_y[(size_t)N_ATOMS * NF];
__device__ __align__(16) unsigned char g_Bhi[BTILE_BYTES];
__device__ __align__(16) unsigned char g_Blo[BTILE_BYTES];
__device__ __align__(16) unsigned char g_W1h[W1TILE_BYTES];
__device__ __align__(16) unsigned char g_W1l[W1TILE_BYTES];

__device__ __forceinline__ float sspf(float v) {
    return fmaxf(v, 0.f) + log1pf(__expf(-fabsf(v))) - 0.6931471805599453f;
}

__device__ __forceinline__ uint32_t smem_u32(const void* p) {
    uint32_t a;
    asm("{ .reg .u64 t; cvta.to.shared.u64 t, %1; cvt.u32.u64 %0, t; }" : "=r"(a) : "l"(p));
    return a;
}

__device__ __forceinline__ void ldsm_x4(uint32_t addr, uint32_t r[4]) {
    asm volatile("ldmatrix.sync.aligned.m8n8.x4.shared.b16 {%0,%1,%2,%3}, [%4];"
                 : "=r"(r[0]), "=r"(r[1]), "=r"(r[2]), "=r"(r[3]) : "r"(addr));
}

__device__ __forceinline__ void mma_bf16(float c[4], const uint32_t a[4],
                                         uint32_t b0, uint32_t b1) {
    asm volatile(
        "mma.sync.aligned.m16n8k16.row.col.f32.bf16.bf16.f32 "
        "{%0,%1,%2,%3}, {%4,%5,%6,%7}, {%8,%9}, {%0,%1,%2,%3};"
        : "+f"(c[0]), "+f"(c[1]), "+f"(c[2]), "+f"(c[3])
        : "r"(a[0]), "r"(a[1]), "r"(a[2]), "r"(a[3]), "r"(b0), "r"(b1));
}

// pack two f32 -> bf16x2 (x -> low 16, y -> high 16)
__device__ __forceinline__ uint32_t pack2bf(float lo, float hi) {
    __nv_bfloat162 v = __float22bfloat162_rn(make_float2(lo, hi));
    return *reinterpret_cast<uint32_t*>(&v);
}

// ---------------------------------------------------------------------------
// prep kernels
// ---------------------------------------------------------------------------
__global__ void prep_w2_kernel(const float* __restrict__ W2) {
    int i = blockIdx.x * blockDim.x + threadIdx.x;
    if (i >= 16384) return;
    int k = i >> 7, n = i & 127;
    float v = W2[k * 128 + n];
    __nv_bfloat16 hi = __float2bfloat16(v);
    __nv_bfloat16 lo = __float2bfloat16(v - __bfloat162float(hi));
    uint32_t off = (uint32_t)n * (KSTR * 2) + (uint32_t)k * 2;
    *(__nv_bfloat16*)(g_Bhi + off) = hi;
    *(__nv_bfloat16*)(g_Blo + off) = lo;
}

__global__ void prep_w1_kernel(const float* __restrict__ W1) {
    int i = blockIdx.x * blockDim.x + threadIdx.x;
    if (i >= 128 * W1STR) return;
    int n = i / W1STR, k = i % W1STR;
    float v = (k < NRBF) ? W1[k * 128 + n] : 0.f;
    __nv_bfloat16 hi = __float2bfloat16(v);
    __nv_bfloat16 lo = __float2bfloat16(v - __bfloat162float(hi));
    uint32_t off = (uint32_t)n * (W1STR * 2) + (uint32_t)k * 2;
    *(__nv_bfloat16*)(g_W1h + off) = hi;
    *(__nv_bfloat16*)(g_W1l + off) = lo;
}

// ---------------------------------------------------------------------------
// h = x @ W_in2f  (512 threads, 4x8 micro-tile) + zero g_y slice
// ---------------------------------------------------------------------------
__global__ void __launch_bounds__(512, 1)
h_kernel(const float* __restrict__ x, const float* __restrict__ W) {
    extern __shared__ float sm[];
    float* sx = sm;
    float* sW = sm + 128 * TSTRIDE;

    const int tid = threadIdx.x;
    const int tx = tid & 15, ty = tid >> 4;
    const int c0 = tx * 8, r0 = ty * 4;
    const int rbase = blockIdx.x * 128;

    // zero this block's slice of g_y (replaces zero_y_kernel)
    {
        float4 z = make_float4(0.f, 0.f, 0.f, 0.f);
        for (int i = tid; i < 128 * 32; i += 512) {
            int r = rbase + (i >> 5);
            if (r < N_ATOMS)
                reinterpret_cast<float4*>(g_y)[(size_t)r * 32 + (i & 31)] = z;
        }
    }

    for (int i = tid; i < 128 * 32; i += 512)
        reinterpret_cast<float4*>(sW)[i] = reinterpret_cast<const float4*>(W)[i];
    for (int i = tid; i < 128 * 32; i += 512) {
        int r = i >> 5, c4 = (i & 31) * 4;
        float4 v = make_float4(0.f, 0.f, 0.f, 0.f);
        if (rbase + r < N_ATOMS)
            v = reinterpret_cast<const float4*>(x)[(size_t)(rbase + r) * 32 + (i & 31)];
        float* d = &sx[r * TSTRIDE + c4];
        d[0] = v.x; d[1] = v.y; d[2] = v.z; d[3] = v.w;
    }
    __syncthreads();

    float acc[4][8];
#pragma unroll
    for (int i = 0; i < 4; i++)
#pragma unroll
        for (int j = 0; j < 8; j++) acc[i][j] = 0.f;

    for (int k = 0; k < 128; k++) {
        float a[4];
#pragma unroll
        for (int i = 0; i < 4; i++) a[i] = sx[(r0 + i) * TSTRIDE + k];
        float4 w0 = *reinterpret_cast<const float4*>(&sW[k * 128 + c0]);
        float4 w1 = *reinterpret_cast<const float4*>(&sW[k * 128 + c0 + 4]);
        float w[8] = {w0.x, w0.y, w0.z, w0.w, w1.x, w1.y, w1.z, w1.w};
#pragma unroll
        for (int i = 0; i < 4; i++)
#pragma unroll
            for (int j = 0; j < 8; j++) acc[i][j] = fmaf(a[i], w[j], acc[i][j]);
    }

#pragma unroll
    for (int i = 0; i < 4; i++) {
        int r = rbase + r0 + i;
        if (r < N_ATOMS) {
            float4 o0 = make_float4(acc[i][0], acc[i][1], acc[i][2], acc[i][3]);
            float4 o1 = make_float4(acc[i][4], acc[i][5], acc[i][6], acc[i][7]);
            float4* dst = reinterpret_cast<float4*>(&g_h[(size_t)r * 128 + c0]);
            dst[0] = o0; dst[1] = o1;
        }
    }
}

// ---------------------------------------------------------------------------
// Persistent edge kernel: 2 CTAs/SM, B/W1 loaded once, grid-stride over tiles.
// smem (bytes):
//   0      : B_hi (34816)
//   34816  : B_lo (34816)
//   69632  : f_hi (10240)  \  st (18432B @69632) aliases f region after GEMM1
//   79872  : f_lo (10240)  /
//   90112  : W1_hi (10240)
//   100352 : W1_lo (10240)
//   110592 : sb1(512) sb2(512) src(512) sii(512) sjj(512)  -> 113152
// ---------------------------------------------------------------------------
#define OFF_BHI  0
#define OFF_BLO  34816
#define OFF_FH   69632
#define OFF_FL   79872
#define OFF_W1H  90112
#define OFF_W1L  100352
#define OFF_ST   69632
#define OFF_B1   110592
#define OFF_B2   111104
#define OFF_RC   111616
#define OFF_II   112128
#define OFF_JJ   112640
#define SMEM_EDGE 113152
#define STSTR 36

__global__ void __launch_bounds__(256, 2)
edge_kernel(const float* __restrict__ f_ij, const float* __restrict__ rcut,
            const int* __restrict__ idx_i, const int* __restrict__ idx_j,
            const float* __restrict__ b1, const float* __restrict__ b2) {
    extern __shared__ __align__(16) unsigned char smraw[];
    const int tid = threadIdx.x;
    const int wid = tid >> 5, lane = tid & 31;
    const uint32_t sbase = smem_u32(smraw);

    float* sb1  = (float*)(smraw + OFF_B1);
    float* sb2  = (float*)(smraw + OFF_B2);
    float* src  = (float*)(smraw + OFF_RC);
    int*   sii  = (int*)(smraw + OFF_II);
    int*   sjj  = (int*)(smraw + OFF_JJ);
    float* st   = (float*)(smraw + OFF_ST);

    // ---- one-time staging: B images, W1 images, biases
    {
        uint4* d1 = (uint4*)(smraw + OFF_BHI);
        uint4* d2 = (uint4*)(smraw + OFF_BLO);
        const uint4* s1 = (const uint4*)g_Bhi;
        const uint4* s2 = (const uint4*)g_Blo;
        for (int i = tid; i < BTILE_BYTES / 16; i += 256) { d1[i] = s1[i]; d2[i] = s2[i]; }
        uint4* w1 = (uint4*)(smraw + OFF_W1H);
        uint4* w2 = (uint4*)(smraw + OFF_W1L);
        const uint4* t1 = (const uint4*)g_W1h;
        const uint4* t2 = (const uint4*)g_W1l;
        for (int i = tid; i < W1TILE_BYTES / 16; i += 256) { w1[i] = t1[i]; w2[i] = t2[i]; }
        if (tid < 128) { sb1[tid] = b1[tid]; sb2[tid] = b2[tid]; }
    }

    const int q = lane & 3, gr = lane >> 2;
    const int r0 = wid * 16 + gr, r1 = r0 + 8;
    const int koff = (lane >> 4) << 3;
    const int nlo = lane & 15;
    const int stx = tid & 15;      // scatter: 2 cols
    const int sty = tid >> 4;      // scatter: 8 edges
    const int fe = tid >> 1, fk0 = (tid & 1) * 10;

    // ---- prefetch first tile
    int tile = blockIdx.x;
    float2 fv[5];
    float prc = 0.f; int pii = 0, pjj = 0;
    {
        const float2* fg = (const float2*)(f_ij + (size_t)tile * 128 * NRBF);
        const int fb = fe * 10 + (fk0 >> 1);
#pragma unroll
        for (int j = 0; j < 5; j++) fv[j] = fg[fb + j];
        if (tid < 128) {
            prc = rcut[tile * 128 + tid];
            pii = idx_i[tile * 128 + tid];
            pjj = idx_j[tile * 128 + tid];
        }
    }
    __syncthreads();   // B/W1/biases visible

    for (; tile < NTILES; tile += GRID_EDGE) {
        // ---- write f hi/lo (cols 0..19), zero pad cols 20..31, write misc
        {
            uint32_t* fh = (uint32_t*)(smraw + OFF_FH);
            uint32_t* fl = (uint32_t*)(smraw + OFF_FL);
            const int base = (fe * (W1STR * 2) + fk0 * 2) >> 2;
#pragma unroll
            for (int j = 0; j < 5; j++) {
                float v0 = fv[j].x, v1 = fv[j].y;
                uint32_t h = pack2bf(v0, v1);
                float e0 = v0 - __uint_as_float(h << 16);
                float e1 = v1 - __uint_as_float(h & 0xFFFF0000u);
                fh[base + j] = h;
                fl[base + j] = pack2bf(e0, e1);
            }
            // zero pad: cols 20..31 (bytes 40..63) of row (tid&127) in one buffer
            unsigned char* fb = smraw + (tid < 128 ? OFF_FH : OFF_FL) +
                                (uint32_t)(tid & 127) * (W1STR * 2) + 40;
            *(uint2*)(fb)      = make_uint2(0u, 0u);
            *(uint2*)(fb + 8)  = make_uint2(0u, 0u);
            *(uint2*)(fb + 16) = make_uint2(0u, 0u);
            if (tid < 128) { src[tid] = prc; sii[tid] = pii; sjj[tid] = pjj; }
        }
        __syncthreads();

        // ---- GEMM1 on tensor cores: t = ssp(f @ W1 + b1) -> A fragments
        uint32_t a_hi[8][4], a_lo[8][4];
        {
            float acc1[16][4];
#pragma unroll
            for (int t = 0; t < 16; t++)
#pragma unroll
                for (int j = 0; j < 4; j++) acc1[t][j] = 0.f;

            const uint32_t afh = sbase + OFF_FH + (uint32_t)(wid * 16 + nlo) * (W1STR * 2);
            const uint32_t afl = sbase + OFF_FL + (uint32_t)(wid * 16 + nlo) * (W1STR * 2);
#pragma unroll
            for (int kk = 0; kk < 2; kk++) {
                const uint32_t kb = (uint32_t)(kk * 16 + koff) * 2;
                uint32_t fh4[4], fl4[4];
                ldsm_x4(afh + kb, fh4);
                ldsm_x4(afl + kb, fl4);
#pragma unroll
                for (int ntp = 0; ntp < 8; ntp++) {
                    const uint32_t baddr = (uint32_t)(ntp * 16 + nlo) * (W1STR * 2) + kb;
                    uint32_t wh[4], wl[4];
                    ldsm_x4(sbase + OFF_W1H + baddr, wh);
                    ldsm_x4(sbase + OFF_W1L + baddr, wl);
                    mma_bf16(acc1[2 * ntp],     fh4, wh[0], wh[2]);
                    mma_bf16(acc1[2 * ntp],     fh4, wl[0], wl[2]);
                    mma_bf16(acc1[2 * ntp],     fl4, wh[0], wh[2]);
                    mma_bf16(acc1[2 * ntp + 1], fh4, wh[1], wh[3]);
                    mma_bf16(acc1[2 * ntp + 1], fh4, wl[1], wl[3]);
                    mma_bf16(acc1[2 * ntp + 1], fl4, wh[1], wh[3]);
                }
            }

#pragma unroll
            for (int n = 0; n < 16; n++) {
                const int c0 = 8 * n + 2 * q;
                float2 bv = *(const float2*)(sb1 + c0);
                float t00 = sspf(acc1[n][0] + bv.x);
                float t01 = sspf(acc1[n][1] + bv.y);
                float t10 = sspf(acc1[n][2] + bv.x);
                float t11 = sspf(acc1[n][3] + bv.y);
                uint32_t h0 = pack2bf(t00, t01);
                uint32_t h1 = pack2bf(t10, t11);
                float e00 = t00 - __uint_as_float(h0 << 16);
                float e01 = t01 - __uint_as_float(h0 & 0xFFFF0000u);
                float e10 = t10 - __uint_as_float(h1 << 16);
                float e11 = t11 - __uint_as_float(h1 & 0xFFFF0000u);
                const int kk = n >> 1, hf = (n & 1) * 2;
                a_hi[kk][hf] = h0; a_hi[kk][hf + 1] = h1;
                a_lo[kk][hf] = pack2bf(e00, e01);
                a_lo[kk][hf + 1] = pack2bf(e10, e11);
            }
        }
        __syncthreads();   // f/W1 reads complete; st may alias f region

        // per-tile epilogue constants
        const float rc0 = src[r0], rc1 = src[r1];
        const int   j0 = sjj[r0],  j1 = sjj[r1];
        const float2* const h0p = (const float2*)(g_h + (size_t)j0 * 128);
        const float2* const h1p = (const float2*)(g_h + (size_t)j1 * 128);

        // ---- prefetch next tile (hidden behind GEMM2 passes)
        {
            const int nt_ = tile + GRID_EDGE;
            if (nt_ < NTILES) {
                const float2* fg = (const float2*)(f_ij + (size_t)nt_ * 128 * NRBF);
                const int fb = fe * 10 + (fk0 >> 1);
#pragma unroll
                for (int j = 0; j < 5; j++) fv[j] = fg[fb + j];
                if (tid < 128) {
                    prc = rcut[nt_ * 128 + tid];
                    pii = idx_i[nt_ * 128 + tid];
                    pjj = idx_j[nt_ * 128 + tid];
                }
            }
        }

        // ---- 4 column-quarter passes of GEMM2 + scatter
#pragma unroll
        for (int p = 0; p < 4; p++) {
            const int colbase = p * 32;

            float acc[4][4];
#pragma unroll
            for (int t = 0; t < 4; t++)
#pragma unroll
                for (int j = 0; j < 4; j++) acc[t][j] = 0.f;

#pragma unroll
            for (int kk = 0; kk < 8; kk++) {
                const uint32_t kb = (uint32_t)(kk * 16 + koff) * 2;
#pragma unroll
                for (int np = 0; np < 2; np++) {
                    const int nrow = colbase + np * 16 + nlo;
                    const uint32_t baddr = (uint32_t)nrow * (KSTR * 2) + kb;
                    uint32_t bh[4], bl[4];
                    ldsm_x4(sbase + OFF_BHI + baddr, bh);
                    ldsm_x4(sbase + OFF_BLO + baddr, bl);
                    mma_bf16(acc[2 * np],     a_hi[kk], bh[0], bh[2]);
                    mma_bf16(acc[2 * np],     a_hi[kk], bl[0], bl[2]);
                    mma_bf16(acc[2 * np],     a_lo[kk], bh[0], bh[2]);
                    mma_bf16(acc[2 * np + 1], a_hi[kk], bh[1], bh[3]);
                    mma_bf16(acc[2 * np + 1], a_hi[kk], bl[1], bl[3]);
                    mma_bf16(acc[2 * np + 1], a_lo[kk], bh[1], bh[3]);
                }
            }

            // modulate + stage to st [128][STSTR]
#pragma unroll
            for (int nt = 0; nt < 4; nt++) {
                const int c = colbase + 8 * nt + 2 * q;
                float2 bv = *(const float2*)(sb2 + c);
                float2 hv0 = h0p[c >> 1];
                float2 hv1 = h1p[c >> 1];
                float2 v0, v1;
                v0.x = (acc[nt][0] + bv.x) * rc0 * hv0.x;
                v0.y = (acc[nt][1] + bv.y) * rc0 * hv0.y;
                v1.x = (acc[nt][2] + bv.x) * rc1 * hv1.x;
                v1.y = (acc[nt][3] + bv.y) * rc1 * hv1.y;
                *(float2*)(st + r0 * STSTR + (c - colbase)) = v0;
                *(float2*)(st + r1 * STSTR + (c - colbase)) = v1;
            }
            __syncthreads();

            // scatter: run-accumulate (idx_i sorted), 2 cols per thread
            {
                float2 run = make_float2(0.f, 0.f);
                int cur = -1;
#pragma unroll
                for (int i = 0; i < 8; i++) {
                    const int e = sty * 8 + i;
                    const int ii = sii[e];
                    if (ii != cur) {
                        if (cur >= 0) {
                            float* y0 = g_y + (size_t)cur * 128 + colbase + 2 * stx;
                            atomicAdd(y0, run.x);
                            atomicAdd(y0 + 1, run.y);
                        }
                        cur = ii;
                        run.x = 0.f; run.y = 0.f;
                    }
                    float2 v = *(const float2*)(st + e * STSTR + 2 * stx);
                    run.x += v.x; run.y += v.y;
                }
                float* y0 = g_y + (size_t)cur * 128 + colbase + 2 * stx;
                atomicAdd(y0, run.x);
                atomicAdd(y0 + 1, run.y);
            }
            __syncthreads();
        }
    }
}

// ---------------------------------------------------------------------------
// out = ssp(y @ W_o1 + b_o1) @ W_o2 + b_o2   (512 threads, 4x8 micro-tile)
// ---------------------------------------------------------------------------
__global__ void __launch_bounds__(512, 1)
out_kernel(const float* __restrict__ Wo1, const float* __restrict__ bo1,
           const float* __restrict__ Wo2, const float* __restrict__ bo2,
           float* __restrict__ out) {
    extern __shared__ float sm[];
    float* sy = sm;
    float* sW = sm + 128 * TSTRIDE;
    float* sb = sW + 16384;

    const int tid = threadIdx.x;
    const int tx = tid & 15, ty = tid >> 4;
    const int c0 = tx * 8, r0 = ty * 4;
    const int rbase = blockIdx.x * 128;

    for (int i = tid; i < 4096; i += 512)
        reinterpret_cast<float4*>(sW)[i] = reinterpret_cast<const float4*>(Wo1)[i];
    if (tid < 128) sb[tid] = bo1[tid];
    for (int i = tid; i < 128 * 32; i += 512) {
        int r = i >> 5, c4 = (i & 31) * 4;
        float4 v = make_float4(0.f, 0.f, 0.f, 0.f);
        if (rbase + r < N_ATOMS)
            v = reinterpret_cast<const float4*>(g_y)[(size_t)(rbase + r) * 32 + (i & 31)];
        float* d = &sy[r * TSTRIDE + c4];
        d[0] = v.x; d[1] = v.y; d[2] = v.z; d[3] = v.w;
    }
    __syncthreads();

    float acc[4][8];
#pragma unroll
    for (int i = 0; i < 4; i++)
#pragma unroll
        for (int j = 0; j < 8; j++) acc[i][j] = 0.f;

    for (int k = 0; k < 128; k++) {
        float a[4];
#pragma unroll
        for (int i = 0; i < 4; i++) a[i] = sy[(r0 + i) * TSTRIDE + k];
        float4 w0 = *reinterpret_cast<const float4*>(&sW[k * 128 + c0]);
        float4 w1 = *reinterpret_cast<const float4*>(&sW[k * 128 + c0 + 4]);
        float w[8] = {w0.x, w0.y, w0.z, w0.w, w1.x, w1.y, w1.z, w1.w};
#pragma unroll
        for (int i = 0; i < 4; i++)
#pragma unroll
            for (int j = 0; j < 8; j++) acc[i][j] = fmaf(a[i], w[j], acc[i][j]);
    }
    __syncthreads();

#pragma unroll
    for (int i = 0; i < 4; i++)
#pragma unroll
        for (int j = 0; j < 8; j++)
            sy[(r0 + i) * TSTRIDE + c0 + j] = sspf(acc[i][j] + sb[c0 + j]);
    __syncthreads();

    for (int i = tid; i < 4096; i += 512)
        reinterpret_cast<float4*>(sW)[i] = reinterpret_cast<const float4*>(Wo2)[i];
    if (tid < 128) sb[tid] = bo2[tid];
    __syncthreads();

    float acc2[4][8];
#pragma unroll
    for (int i = 0; i < 4; i++)
#pragma unroll
        for (int j = 0; j < 8; j++) acc2[i][j] = 0.f;

    for (int k = 0; k < 128; k++) {
        float a[4];
#pragma unroll
        for (int i = 0; i < 4; i++) a[i] = sy[(r0 + i) * TSTRIDE + k];
        float4 w0 = *reinterpret_cast<const float4*>(&sW[k * 128 + c0]);
        float4 w1 = *reinterpret_cast<const float4*>(&sW[k * 128 + c0 + 4]);
        float w[8] = {w0.x, w0.y, w0.z, w0.w, w1.x, w1.y, w1.z, w1.w};
#pragma unroll
        for (int i = 0; i < 4; i++)
#pragma unroll
            for (int j = 0; j < 8; j++) acc2[i][j] = fmaf(a[i], w[j], acc2[i][j]);
    }

#pragma unroll
    for (int i = 0; i < 4; i++) {
        int r = rbase + r0 + i;
        if (r < N_ATOMS) {
            float4 o0 = make_float4(acc2[i][0] + sb[c0 + 0], acc2[i][1] + sb[c0 + 1],
                                    acc2[i][2] + sb[c0 + 2], acc2[i][3] + sb[c0 + 3]);
            float4 o1 = make_float4(acc2[i][4] + sb[c0 + 4], acc2[i][5] + sb[c0 + 5],
                                    acc2[i][6] + sb[c0 + 6], acc2[i][7] + sb[c0 + 7]);
            float4* dst = reinterpret_cast<float4*>(&out[(size_t)r * 128 + c0]);
            dst[0] = o0; dst[1] = o1;
        }
    }
}

// ---------------------------------------------------------------------------
extern "C" void kernel_launch(void* const* d_in, const int* in_sizes, int n_in,
                              void* d_out, int out_size) {
    const float* x      = (const float*)d_in[0];
    const float* f_ij   = (const float*)d_in[1];
    const float* rcut   = (const float*)d_in[2];
    const int*   idx_i  = (const int*)d_in[3];
    const int*   idx_j  = (const int*)d_in[4];
    const float* W_in2f = (const float*)d_in[5];
    const float* W_f1   = (const float*)d_in[6];
    const float* b_f1   = (const float*)d_in[7];
    const float* W_f2   = (const float*)d_in[8];
    const float* b_f2   = (const float*)d_in[9];
    const float* W_o1   = (const float*)d_in[10];
    const float* b_o1   = (const float*)d_in[11];
    const float* W_o2   = (const float*)d_in[12];
    const float* b_o2   = (const float*)d_in[13];
    float* out = (float*)d_out;

    const int smemA = (128 * TSTRIDE + 128 * 128) * 4;
    const int smemC = (128 * TSTRIDE + 128 * 128 + 128) * 4;

    cudaFuncSetAttribute(h_kernel, cudaFuncAttributeMaxDynamicSharedMemorySize, smemA);
    cudaFuncSetAttribute(edge_kernel, cudaFuncAttributeMaxDynamicSharedMemorySize, SMEM_EDGE);
    cudaFuncSetAttribute(out_kernel, cudaFuncAttributeMaxDynamicSharedMemorySize, smemC);

    prep_w2_kernel<<<64, 256>>>(W_f2);
    prep_w1_kernel<<<20, 256>>>(W_f1);
    h_kernel<<<(N_ATOMS + 127) / 128, 512, smemA>>>(x, W_in2f);
    edge_kernel<<<GRID_EDGE, 256, SMEM_EDGE>>>(f_ij, rcut, idx_i, idx_j,
                                               b_f1, b_f2);
    out_kernel<<<(N_ATOMS + 127) / 128, 512, smemC>>>(W_o1, b_o1, W_o2, b_o2, out);
}

// round 11
// speedup vs baseline: 1.1768x; 1.1768x over previous
#include <cuda_runtime.h>
#include <cuda_bf16.h>
#include <cstdint>

#define N_ATOMS 50000
#define N_EDGES 1600000
#define NF      128
#define NRBF    20
#define TSTRIDE 130
#define NTILES  (N_EDGES / 128)   // 12500

// B (W2^T) bf16 tile row stride in elements (128 data + 8 pad -> 272B rows)
#define KSTR 136
#define BTILE_BYTES (128 * KSTR * 2)   // 34816
// W1^T / f tile row stride: 40 bf16 = 80B (banks stride 20 -> conflict-free ldsm)
#define W1STR 40
#define W1TILE_BYTES (128 * W1STR * 2) // 10240

// ---------------- device globals (no allocation allowed) -------------------
__device__ float g_h[(size_t)N_ATOMS * NF];
__device__ float g_y[(size_t)N_ATOMS * NF];
__device__ __align__(16) unsigned char g_Bhi[BTILE_BYTES];
__device__ __align__(16) unsigned char g_Blo[BTILE_BYTES];
__device__ __align__(16) unsigned char g_W1h[W1TILE_BYTES];
__device__ __align__(16) unsigned char g_W1l[W1TILE_BYTES];

// fast shifted-softplus: max(x,0) + ln2*(log2(1+2^(-|x|*log2e)) - 1)
// abs err ~1e-7 (MUFU.EX2/LG2), vs log1pf's ~25-instr expansion
__device__ __forceinline__ float sspf(float v) {
    float e = exp2f(-fabsf(v) * 1.4426950408889634f);
    return fmaxf(v, 0.f) + 0.6931471805599453f * (__log2f(1.f + e) - 1.f);
}

__device__ __forceinline__ uint32_t smem_u32(const void* p) {
    uint32_t a;
    asm("{ .reg .u64 t; cvta.to.shared.u64 t, %1; cvt.u32.u64 %0, t; }" : "=r"(a) : "l"(p));
    return a;
}

__device__ __forceinline__ void ldsm_x4(uint32_t addr, uint32_t r[4]) {
    asm volatile("ldmatrix.sync.aligned.m8n8.x4.shared.b16 {%0,%1,%2,%3}, [%4];"
                 : "=r"(r[0]), "=r"(r[1]), "=r"(r[2]), "=r"(r[3]) : "r"(addr));
}

__device__ __forceinline__ void mma_bf16(float c[4], const uint32_t a[4],
                                         uint32_t b0, uint32_t b1) {
    asm volatile(
        "mma.sync.aligned.m16n8k16.row.col.f32.bf16.bf16.f32 "
        "{%0,%1,%2,%3}, {%4,%5,%6,%7}, {%8,%9}, {%0,%1,%2,%3};"
        : "+f"(c[0]), "+f"(c[1]), "+f"(c[2]), "+f"(c[3])
        : "r"(a[0]), "r"(a[1]), "r"(a[2]), "r"(a[3]), "r"(b0), "r"(b1));
}

// pack two f32 -> bf16x2 (x -> low 16, y -> high 16)
__device__ __forceinline__ uint32_t pack2bf(float lo, float hi) {
    __nv_bfloat162 v = __float22bfloat162_rn(make_float2(lo, hi));
    return *reinterpret_cast<uint32_t*>(&v);
}

// ---------------------------------------------------------------------------
// prep kernels
// ---------------------------------------------------------------------------
__global__ void prep_w2_kernel(const float* __restrict__ W2) {
    int i = blockIdx.x * blockDim.x + threadIdx.x;
    if (i >= 16384) return;
    int k = i >> 7, n = i & 127;
    float v = W2[k * 128 + n];
    __nv_bfloat16 hi = __float2bfloat16(v);
    __nv_bfloat16 lo = __float2bfloat16(v - __bfloat162float(hi));
    uint32_t off = (uint32_t)n * (KSTR * 2) + (uint32_t)k * 2;
    *(__nv_bfloat16*)(g_Bhi + off) = hi;
    *(__nv_bfloat16*)(g_Blo + off) = lo;
}

__global__ void prep_w1_kernel(const float* __restrict__ W1) {
    int i = blockIdx.x * blockDim.x + threadIdx.x;
    if (i >= 128 * W1STR) return;
    int n = i / W1STR, k = i % W1STR;
    float v = (k < NRBF) ? W1[k * 128 + n] : 0.f;
    __nv_bfloat16 hi = __float2bfloat16(v);
    __nv_bfloat16 lo = __float2bfloat16(v - __bfloat162float(hi));
    uint32_t off = (uint32_t)n * (W1STR * 2) + (uint32_t)k * 2;
    *(__nv_bfloat16*)(g_W1h + off) = hi;
    *(__nv_bfloat16*)(g_W1l + off) = lo;
}

// ---------------------------------------------------------------------------
// h = x @ W_in2f  (512 threads, 4x8 micro-tile) + zero g_y slice
// ---------------------------------------------------------------------------
__global__ void __launch_bounds__(512, 1)
h_kernel(const float* __restrict__ x, const float* __restrict__ W) {
    extern __shared__ float sm[];
    float* sx = sm;
    float* sW = sm + 128 * TSTRIDE;

    const int tid = threadIdx.x;
    const int tx = tid & 15, ty = tid >> 4;
    const int c0 = tx * 8, r0 = ty * 4;
    const int rbase = blockIdx.x * 128;

    {
        float4 z = make_float4(0.f, 0.f, 0.f, 0.f);
        for (int i = tid; i < 128 * 32; i += 512) {
            int r = rbase + (i >> 5);
            if (r < N_ATOMS)
                reinterpret_cast<float4*>(g_y)[(size_t)r * 32 + (i & 31)] = z;
        }
    }

    for (int i = tid; i < 128 * 32; i += 512)
        reinterpret_cast<float4*>(sW)[i] = reinterpret_cast<const float4*>(W)[i];
    for (int i = tid; i < 128 * 32; i += 512) {
        int r = i >> 5, c4 = (i & 31) * 4;
        float4 v = make_float4(0.f, 0.f, 0.f, 0.f);
        if (rbase + r < N_ATOMS)
            v = reinterpret_cast<const float4*>(x)[(size_t)(rbase + r) * 32 + (i & 31)];
        float* d = &sx[r * TSTRIDE + c4];
        d[0] = v.x; d[1] = v.y; d[2] = v.z; d[3] = v.w;
    }
    __syncthreads();

    float acc[4][8];
#pragma unroll
    for (int i = 0; i < 4; i++)
#pragma unroll
        for (int j = 0; j < 8; j++) acc[i][j] = 0.f;

    for (int k = 0; k < 128; k++) {
        float a[4];
#pragma unroll
        for (int i = 0; i < 4; i++) a[i] = sx[(r0 + i) * TSTRIDE + k];
        float4 w0 = *reinterpret_cast<const float4*>(&sW[k * 128 + c0]);
        float4 w1 = *reinterpret_cast<const float4*>(&sW[k * 128 + c0 + 4]);
        float w[8] = {w0.x, w0.y, w0.z, w0.w, w1.x, w1.y, w1.z, w1.w};
#pragma unroll
        for (int i = 0; i < 4; i++)
#pragma unroll
            for (int j = 0; j < 8; j++) acc[i][j] = fmaf(a[i], w[j], acc[i][j]);
    }

#pragma unroll
    for (int i = 0; i < 4; i++) {
        int r = rbase + r0 + i;
        if (r < N_ATOMS) {
            float4 o0 = make_float4(acc[i][0], acc[i][1], acc[i][2], acc[i][3]);
            float4 o1 = make_float4(acc[i][4], acc[i][5], acc[i][6], acc[i][7]);
            float4* dst = reinterpret_cast<float4*>(&g_h[(size_t)r * 128 + c0]);
            dst[0] = o0; dst[1] = o1;
        }
    }
}

// ---------------------------------------------------------------------------
// Edge kernel: per-tile grid, 2 CTAs/SM.  smem (bytes):
//   0      : B_hi (34816)
//   34816  : B_lo (34816)
//   69632  : f_hi (10240)  \  st (18432B @69632) aliases f region after GEMM1
//   79872  : f_lo (10240)  /
//   90112  : W1_hi (10240)
//   100352 : W1_lo (10240)
//   110592 : sb1(512) sb2(512) src(512) sii(512) sjj(512)  -> 113152
// ---------------------------------------------------------------------------
#define OFF_BHI  0
#define OFF_BLO  34816
#define OFF_FH   69632
#define OFF_FL   79872
#define OFF_W1H  90112
#define OFF_W1L  100352
#define OFF_ST   69632
#define OFF_B1   110592
#define OFF_B2   111104
#define OFF_RC   111616
#define OFF_II   112128
#define OFF_JJ   112640
#define SMEM_EDGE 113152
#define STSTR 36

__global__ void __launch_bounds__(256, 2)
edge_kernel(const float* __restrict__ f_ij, const float* __restrict__ rcut,
            const int* __restrict__ idx_i, const int* __restrict__ idx_j,
            const float* __restrict__ b1, const float* __restrict__ b2) {
    extern __shared__ __align__(16) unsigned char smraw[];
    const int tid = threadIdx.x;
    const int wid = tid >> 5, lane = tid & 31;
    const uint32_t sbase = smem_u32(smraw);
    const int ebase = blockIdx.x * 128;

    float* sb1  = (float*)(smraw + OFF_B1);
    float* sb2  = (float*)(smraw + OFF_B2);
    float* src  = (float*)(smraw + OFF_RC);
    int*   sii  = (int*)(smraw + OFF_II);
    int*   sjj  = (int*)(smraw + OFF_JJ);
    float* st   = (float*)(smraw + OFF_ST);

    // f / rcut / idx LDG into registers (overlaps the B/W1 staging below)
    const int fe = tid >> 1, fk0 = (tid & 1) * 10;
    float2 fv[5];
    {
        const float2* fg = (const float2*)(f_ij + (size_t)ebase * NRBF);
        const int fb = fe * 10 + (fk0 >> 1);
#pragma unroll
        for (int j = 0; j < 5; j++) fv[j] = fg[fb + j];
    }
    float prc = 0.f; int pii = 0, pjj = 0;
    if (tid < 128) {
        prc = rcut[ebase + tid];
        pii = idx_i[ebase + tid];
        pjj = idx_j[ebase + tid];
    }

    // ---- single staging phase: B, W1, f hi/lo (+pad zero), biases, misc
    {
        uint4* d1 = (uint4*)(smraw + OFF_BHI);
        uint4* d2 = (uint4*)(smraw + OFF_BLO);
        const uint4* s1 = (const uint4*)g_Bhi;
        const uint4* s2 = (const uint4*)g_Blo;
        for (int i = tid; i < BTILE_BYTES / 16; i += 256) { d1[i] = s1[i]; d2[i] = s2[i]; }
        uint4* w1 = (uint4*)(smraw + OFF_W1H);
        uint4* w2 = (uint4*)(smraw + OFF_W1L);
        const uint4* t1 = (const uint4*)g_W1h;
        const uint4* t2 = (const uint4*)g_W1l;
        for (int i = tid; i < W1TILE_BYTES / 16; i += 256) { w1[i] = t1[i]; w2[i] = t2[i]; }

        // f convert: cols fk0..fk0+9 of row fe in both buffers
        uint32_t* fh = (uint32_t*)(smraw + OFF_FH);
        uint32_t* fl = (uint32_t*)(smraw + OFF_FL);
        const int base = (fe * (W1STR * 2) + fk0 * 2) >> 2;
#pragma unroll
        for (int j = 0; j < 5; j++) {
            float v0 = fv[j].x, v1 = fv[j].y;
            uint32_t h = pack2bf(v0, v1);
            float e0 = v0 - __uint_as_float(h << 16);
            float e1 = v1 - __uint_as_float(h & 0xFFFF0000u);
            fh[base + j] = h;
            fl[base + j] = pack2bf(e0, e1);
        }
        // zero pad cols 20..31 (bytes 40..63): disjoint from convert writes
        unsigned char* fb = smraw + (tid < 128 ? OFF_FH : OFF_FL) +
                            (uint32_t)(tid & 127) * (W1STR * 2) + 40;
        *(uint2*)(fb)      = make_uint2(0u, 0u);
        *(uint2*)(fb + 8)  = make_uint2(0u, 0u);
        *(uint2*)(fb + 16) = make_uint2(0u, 0u);

        if (tid < 128) {
            sb1[tid] = b1[tid];
            sb2[tid] = b2[tid];
            src[tid] = prc; sii[tid] = pii; sjj[tid] = pjj;
        }
    }
    __syncthreads();

    const int q = lane & 3, gr = lane >> 2;
    const int r0 = wid * 16 + gr, r1 = r0 + 8;
    const int koff = (lane >> 4) << 3;
    const int nlo = lane & 15;
    const int stx = tid & 15;      // scatter: 2 cols
    const int sty = tid >> 4;      // scatter: 8 edges

    // ---- GEMM1 on tensor cores: t = ssp(f @ W1 + b1) -> A fragments
    uint32_t a_hi[8][4], a_lo[8][4];
    {
        float acc1[16][4];
#pragma unroll
        for (int t = 0; t < 16; t++)
#pragma unroll
            for (int j = 0; j < 4; j++) acc1[t][j] = 0.f;

        const uint32_t afh = sbase + OFF_FH + (uint32_t)(wid * 16 + nlo) * (W1STR * 2);
        const uint32_t afl = sbase + OFF_FL + (uint32_t)(wid * 16 + nlo) * (W1STR * 2);
#pragma unroll
        for (int kk = 0; kk < 2; kk++) {
            const uint32_t kb = (uint32_t)(kk * 16 + koff) * 2;
            uint32_t fh4[4], fl4[4];
            ldsm_x4(afh + kb, fh4);
            ldsm_x4(afl + kb, fl4);
#pragma unroll
            for (int ntp = 0; ntp < 8; ntp++) {
                const uint32_t baddr = (uint32_t)(ntp * 16 + nlo) * (W1STR * 2) + kb;
                uint32_t wh[4], wl[4];
                ldsm_x4(sbase + OFF_W1H + baddr, wh);
                ldsm_x4(sbase + OFF_W1L + baddr, wl);
                // interleave the two accumulators (2-way ILP on HMMA chains)
                mma_bf16(acc1[2 * ntp],     fh4, wh[0], wh[2]);
                mma_bf16(acc1[2 * ntp + 1], fh4, wh[1], wh[3]);
                mma_bf16(acc1[2 * ntp],     fh4, wl[0], wl[2]);
                mma_bf16(acc1[2 * ntp + 1], fh4, wl[1], wl[3]);
                mma_bf16(acc1[2 * ntp],     fl4, wh[0], wh[2]);
                mma_bf16(acc1[2 * ntp + 1], fl4, wh[1], wh[3]);
            }
        }

#pragma unroll
        for (int n = 0; n < 16; n++) {
            const int c0 = 8 * n + 2 * q;
            float2 bv = *(const float2*)(sb1 + c0);
            float t00 = sspf(acc1[n][0] + bv.x);
            float t01 = sspf(acc1[n][1] + bv.y);
            float t10 = sspf(acc1[n][2] + bv.x);
            float t11 = sspf(acc1[n][3] + bv.y);
            uint32_t h0 = pack2bf(t00, t01);
            uint32_t h1 = pack2bf(t10, t11);
            float e00 = t00 - __uint_as_float(h0 << 16);
            float e01 = t01 - __uint_as_float(h0 & 0xFFFF0000u);
            float e10 = t10 - __uint_as_float(h1 << 16);
            float e11 = t11 - __uint_as_float(h1 & 0xFFFF0000u);
            const int kk = n >> 1, hf = (n & 1) * 2;
            a_hi[kk][hf] = h0; a_hi[kk][hf + 1] = h1;
            a_lo[kk][hf] = pack2bf(e00, e01);
            a_lo[kk][hf + 1] = pack2bf(e10, e11);
        }
    }
    __syncthreads();   // f/W1 reads complete; st may alias f region

    // per-tile epilogue constants
    const float rc0 = src[r0], rc1 = src[r1];
    const int   j0 = sjj[r0],  j1 = sjj[r1];
    const float2* const h0p = (const float2*)(g_h + (size_t)j0 * 128);
    const float2* const h1p = (const float2*)(g_h + (size_t)j1 * 128);

    // ---- 4 column-quarter passes of GEMM2 + scatter
#pragma unroll
    for (int p = 0; p < 4; p++) {
        const int colbase = p * 32;

        float acc[4][4];
#pragma unroll
        for (int t = 0; t < 4; t++)
#pragma unroll
            for (int j = 0; j < 4; j++) acc[t][j] = 0.f;

#pragma unroll
        for (int kk = 0; kk < 8; kk++) {
            const uint32_t kb = (uint32_t)(kk * 16 + koff) * 2;
#pragma unroll
            for (int np = 0; np < 2; np++) {
                const int nrow = colbase + np * 16 + nlo;
                const uint32_t baddr = (uint32_t)nrow * (KSTR * 2) + kb;
                uint32_t bh[4], bl[4];
                ldsm_x4(sbase + OFF_BHI + baddr, bh);
                ldsm_x4(sbase + OFF_BLO + baddr, bl);
                // interleave the two accumulators (2-way ILP on HMMA chains)
                mma_bf16(acc[2 * np],     a_hi[kk], bh[0], bh[2]);
                mma_bf16(acc[2 * np + 1], a_hi[kk], bh[1], bh[3]);
                mma_bf16(acc[2 * np],     a_hi[kk], bl[0], bl[2]);
                mma_bf16(acc[2 * np + 1], a_hi[kk], bl[1], bl[3]);
                mma_bf16(acc[2 * np],     a_lo[kk], bh[0], bh[2]);
                mma_bf16(acc[2 * np + 1], a_lo[kk], bh[1], bh[3]);
            }
        }

        // modulate + stage to st [128][STSTR]
#pragma unroll
        for (int nt = 0; nt < 4; nt++) {
            const int c = colbase + 8 * nt + 2 * q;
            float2 bv = *(const float2*)(sb2 + c);
            float2 hv0 = h0p[c >> 1];
            float2 hv1 = h1p[c >> 1];
            float2 v0, v1;
            v0.x = (acc[nt][0] + bv.x) * rc0 * hv0.x;
            v0.y = (acc[nt][1] + bv.y) * rc0 * hv0.y;
            v1.x = (acc[nt][2] + bv.x) * rc1 * hv1.x;
            v1.y = (acc[nt][3] + bv.y) * rc1 * hv1.y;
            *(float2*)(st + r0 * STSTR + (c - colbase)) = v0;
            *(float2*)(st + r1 * STSTR + (c - colbase)) = v1;
        }
        __syncthreads();

        // scatter: run-accumulate (idx_i sorted), 2 cols per thread
        {
            float2 run = make_float2(0.f, 0.f);
            int cur = -1;
#pragma unroll
            for (int i = 0; i < 8; i++) {
                const int e = sty * 8 + i;
                const int ii = sii[e];
                if (ii != cur) {
                    if (cur >= 0) {
                        float* y0 = g_y + (size_t)cur * 128 + colbase + 2 * stx;
                        atomicAdd(y0, run.x);
                        atomicAdd(y0 + 1, run.y);
                    }
                    cur = ii;
                    run.x = 0.f; run.y = 0.f;
                }
                float2 v = *(const float2*)(st + e * STSTR + 2 * stx);
                run.x += v.x; run.y += v.y;
            }
            float* y0 = g_y + (size_t)cur * 128 + colbase + 2 * stx;
            atomicAdd(y0, run.x);
            atomicAdd(y0 + 1, run.y);
        }
        __syncthreads();
    }
}

// ---------------------------------------------------------------------------
// out = ssp(y @ W_o1 + b_o1) @ W_o2 + b_o2   (512 threads, 4x8 micro-tile)
// ---------------------------------------------------------------------------
__global__ void __launch_bounds__(512, 1)
out_kernel(const float* __restrict__ Wo1, const float* __restrict__ bo1,
           const float* __restrict__ Wo2, const float* __restrict__ bo2,
           float* __restrict__ out) {
    extern __shared__ float sm[];
    float* sy = sm;
    float* sW = sm + 128 * TSTRIDE;
    float* sb = sW + 16384;

    const int tid = threadIdx.x;
    const int tx = tid & 15, ty = tid >> 4;
    const int c0 = tx * 8, r0 = ty * 4;
    const int rbase = blockIdx.x * 128;

    for (int i = tid; i < 4096; i += 512)
        reinterpret_cast<float4*>(sW)[i] = reinterpret_cast<const float4*>(Wo1)[i];
    if (tid < 128) sb[tid] = bo1[tid];
    for (int i = tid; i < 128 * 32; i += 512) {
        int r = i >> 5, c4 = (i & 31) * 4;
        float4 v = make_float4(0.f, 0.f, 0.f, 0.f);
        if (rbase + r < N_ATOMS)
            v = reinterpret_cast<const float4*>(g_y)[(size_t)(rbase + r) * 32 + (i & 31)];
        float* d = &sy[r * TSTRIDE + c4];
        d[0] = v.x; d[1] = v.y; d[2] = v.z; d[3] = v.w;
    }
    __syncthreads();

    float acc[4][8];
#pragma unroll
    for (int i = 0; i < 4; i++)
#pragma unroll
        for (int j = 0; j < 8; j++) acc[i][j] = 0.f;

    for (int k = 0; k < 128; k++) {
        float a[4];
#pragma unroll
        for (int i = 0; i < 4; i++) a[i] = sy[(r0 + i) * TSTRIDE + k];
        float4 w0 = *reinterpret_cast<const float4*>(&sW[k * 128 + c0]);
        float4 w1 = *reinterpret_cast<const float4*>(&sW[k * 128 + c0 + 4]);
        float w[8] = {w0.x, w0.y, w0.z, w0.w, w1.x, w1.y, w1.z, w1.w};
#pragma unroll
        for (int i = 0; i < 4; i++)
#pragma unroll
            for (int j = 0; j < 8; j++) acc[i][j] = fmaf(a[i], w[j], acc[i][j]);
    }
    __syncthreads();

#pragma unroll
    for (int i = 0; i < 4; i++)
#pragma unroll
        for (int j = 0; j < 8; j++)
            sy[(r0 + i) * TSTRIDE + c0 + j] = sspf(acc[i][j] + sb[c0 + j]);
    __syncthreads();

    for (int i = tid; i < 4096; i += 512)
        reinterpret_cast<float4*>(sW)[i] = reinterpret_cast<const float4*>(Wo2)[i];
    if (tid < 128) sb[tid] = bo2[tid];
    __syncthreads();

    float acc2[4][8];
#pragma unroll
    for (int i = 0; i < 4; i++)
#pragma unroll
        for (int j = 0; j < 8; j++) acc2[i][j] = 0.f;

    for (int k = 0; k < 128; k++) {
        float a[4];
#pragma unroll
        for (int i = 0; i < 4; i++) a[i] = sy[(r0 + i) * TSTRIDE + k];
        float4 w0 = *reinterpret_cast<const float4*>(&sW[k * 128 + c0]);
        float4 w1 = *reinterpret_cast<const float4*>(&sW[k * 128 + c0 + 4]);
        float w[8] = {w0.x, w0.y, w0.z, w0.w, w1.x, w1.y, w1.z, w1.w};
#pragma unroll
        for (int i = 0; i < 4; i++)
#pragma unroll
            for (int j = 0; j < 8; j++) acc2[i][j] = fmaf(a[i], w[j], acc2[i][j]);
    }

#pragma unroll
    for (int i = 0; i < 4; i++) {
        int r = rbase + r0 + i;
        if (r < N_ATOMS) {
            float4 o0 = make_float4(acc2[i][0] + sb[c0 + 0], acc2[i][1] + sb[c0 + 1],
                                    acc2[i][2] + sb[c0 + 2], acc2[i][3] + sb[c0 + 3]);
            float4 o1 = make_float4(acc2[i][4] + sb[c0 + 4], acc2[i][5] + sb[c0 + 5],
                                    acc2[i][6] + sb[c0 + 6], acc2[i][7] + sb[c0 + 7]);
            float4* dst = reinterpret_cast<float4*>(&out[(size_t)r * 128 + c0]);
            dst[0] = o0; dst[1] = o1;
        }
    }
}

// ---------------------------------------------------------------------------
extern "C" void kernel_launch(void* const* d_in, const int* in_sizes, int n_in,
                              void* d_out, int out_size) {
    const float* x      = (const float*)d_in[0];
    const float* f_ij   = (const float*)d_in[1];
    const float* rcut   = (const float*)d_in[2];
    const int*   idx_i  = (const int*)d_in[3];
    const int*   idx_j  = (const int*)d_in[4];
    const float* W_in2f = (const float*)d_in[5];
    const float* W_f1   = (const float*)d_in[6];
    const float* b_f1   = (const float*)d_in[7];
    const float* W_f2   = (const float*)d_in[8];
    const float* b_f2   = (const float*)d_in[9];
    const float* W_o1   = (const float*)d_in[10];
    const float* b_o1   = (const float*)d_in[11];
    const float* W_o2   = (const float*)d_in[12];
    const float* b_o2   = (const float*)d_in[13];
    float* out = (float*)d_out;

    const int smemA = (128 * TSTRIDE + 128 * 128) * 4;
    const int smemC = (128 * TSTRIDE + 128 * 128 + 128) * 4;

    cudaFuncSetAttribute(h_kernel, cudaFuncAttributeMaxDynamicSharedMemorySize, smemA);
    cudaFuncSetAttribute(edge_kernel, cudaFuncAttributeMaxDynamicSharedMemorySize, SMEM_EDGE);
    cudaFuncSetAttribute(out_kernel, cudaFuncAttributeMaxDynamicSharedMemorySize, smemC);

    prep_w2_kernel<<<64, 256>>>(W_f2);
    prep_w1_kernel<<<20, 256>>>(W_f1);
    h_kernel<<<(N_ATOMS + 127) / 128, 512, smemA>>>(x, W_in2f);
    edge_kernel<<<NTILES, 256, SMEM_EDGE>>>(f_ij, rcut, idx_i, idx_j,
                                            b_f1, b_f2);
    out_kernel<<<(N_ATOMS + 127) / 128, 512, smemC>>>(W_o1, b_o1, W_o2, b_o2, out);
}

// round 12
// speedup vs baseline: 1.2062x; 1.0250x over previous
#include <cuda_runtime.h>
#include <cuda_bf16.h>
#include <cstdint>

#define N_ATOMS 50000
#define N_EDGES 1600000
#define NF      128
#define NRBF    20
#define TSTRIDE 130
#define NTILES  (N_EDGES / 128)   // 12500

// B (W2^T) bf16 tile row stride in elements (128 data + 8 pad -> 272B rows)
#define KSTR 136
#define BTILE_BYTES (128 * KSTR * 2)   // 34816
// W1^T / f tile row stride: 40 bf16 = 80B (banks stride 20 -> conflict-free ldsm)
#define W1STR 40
#define W1TILE_BYTES (128 * W1STR * 2) // 10240

// ---------------- device globals (no allocation allowed) -------------------
__device__ float g_h[(size_t)N_ATOMS * NF];
__device__ float g_y[(size_t)N_ATOMS * NF];
__device__ __align__(16) unsigned char g_Bhi[BTILE_BYTES];
__device__ __align__(16) unsigned char g_Blo[BTILE_BYTES];
__device__ __align__(16) unsigned char g_W1h[W1TILE_BYTES];
__device__ __align__(16) unsigned char g_W1l[W1TILE_BYTES];

// fast shifted-softplus: max(x,0) + ln2*(log2(1+2^(-|x|*log2e)) - 1)
__device__ __forceinline__ float sspf(float v) {
    float e = exp2f(-fabsf(v) * 1.4426950408889634f);
    return fmaxf(v, 0.f) + 0.6931471805599453f * (__log2f(1.f + e) - 1.f);
}

__device__ __forceinline__ uint32_t smem_u32(const void* p) {
    uint32_t a;
    asm("{ .reg .u64 t; cvta.to.shared.u64 t, %1; cvt.u32.u64 %0, t; }" : "=r"(a) : "l"(p));
    return a;
}

__device__ __forceinline__ void ldsm_x4(uint32_t addr, uint32_t r[4]) {
    asm volatile("ldmatrix.sync.aligned.m8n8.x4.shared.b16 {%0,%1,%2,%3}, [%4];"
                 : "=r"(r[0]), "=r"(r[1]), "=r"(r[2]), "=r"(r[3]) : "r"(addr));
}

__device__ __forceinline__ void mma_bf16(float c[4], const uint32_t a[4],
                                         uint32_t b0, uint32_t b1) {
    asm volatile(
        "mma.sync.aligned.m16n8k16.row.col.f32.bf16.bf16.f32 "
        "{%0,%1,%2,%3}, {%4,%5,%6,%7}, {%8,%9}, {%0,%1,%2,%3};"
        : "+f"(c[0]), "+f"(c[1]), "+f"(c[2]), "+f"(c[3])
        : "r"(a[0]), "r"(a[1]), "r"(a[2]), "r"(a[3]), "r"(b0), "r"(b1));
}

// pack two f32 -> bf16x2 (x -> low 16, y -> high 16)
__device__ __forceinline__ uint32_t pack2bf(float lo, float hi) {
    __nv_bfloat162 v = __float22bfloat162_rn(make_float2(lo, hi));
    return *reinterpret_cast<uint32_t*>(&v);
}

// vector reduction to global (L2-side, no L1 traffic)
__device__ __forceinline__ void red_add_f32x2(float* p, float x, float y) {
    asm volatile("red.global.add.v2.f32 [%0], {%1, %2};"
                 :: "l"(p), "f"(x), "f"(y) : "memory");
}

// ---------------------------------------------------------------------------
// prep kernels
// ---------------------------------------------------------------------------
__global__ void prep_w2_kernel(const float* __restrict__ W2) {
    int i = blockIdx.x * blockDim.x + threadIdx.x;
    if (i >= 16384) return;
    int k = i >> 7, n = i & 127;
    float v = W2[k * 128 + n];
    __nv_bfloat16 hi = __float2bfloat16(v);
    __nv_bfloat16 lo = __float2bfloat16(v - __bfloat162float(hi));
    uint32_t off = (uint32_t)n * (KSTR * 2) + (uint32_t)k * 2;
    *(__nv_bfloat16*)(g_Bhi + off) = hi;
    *(__nv_bfloat16*)(g_Blo + off) = lo;
}

__global__ void prep_w1_kernel(const float* __restrict__ W1) {
    int i = blockIdx.x * blockDim.x + threadIdx.x;
    if (i >= 128 * W1STR) return;
    int n = i / W1STR, k = i % W1STR;
    float v = (k < NRBF) ? W1[k * 128 + n] : 0.f;
    __nv_bfloat16 hi = __float2bfloat16(v);
    __nv_bfloat16 lo = __float2bfloat16(v - __bfloat162float(hi));
    uint32_t off = (uint32_t)n * (W1STR * 2) + (uint32_t)k * 2;
    *(__nv_bfloat16*)(g_W1h + off) = hi;
    *(__nv_bfloat16*)(g_W1l + off) = lo;
}

// ---------------------------------------------------------------------------
// h = x @ W_in2f  (512 threads, 4x8 micro-tile) + zero g_y slice
// ---------------------------------------------------------------------------
__global__ void __launch_bounds__(512, 1)
h_kernel(const float* __restrict__ x, const float* __restrict__ W) {
    extern __shared__ float sm[];
    float* sx = sm;
    float* sW = sm + 128 * TSTRIDE;

    const int tid = threadIdx.x;
    const int tx = tid & 15, ty = tid >> 4;
    const int c0 = tx * 8, r0 = ty * 4;
    const int rbase = blockIdx.x * 128;

    {
        float4 z = make_float4(0.f, 0.f, 0.f, 0.f);
        for (int i = tid; i < 128 * 32; i += 512) {
            int r = rbase + (i >> 5);
            if (r < N_ATOMS)
                reinterpret_cast<float4*>(g_y)[(size_t)r * 32 + (i & 31)] = z;
        }
    }

    for (int i = tid; i < 128 * 32; i += 512)
        reinterpret_cast<float4*>(sW)[i] = reinterpret_cast<const float4*>(W)[i];
    for (int i = tid; i < 128 * 32; i += 512) {
        int r = i >> 5, c4 = (i & 31) * 4;
        float4 v = make_float4(0.f, 0.f, 0.f, 0.f);
        if (rbase + r < N_ATOMS)
            v = reinterpret_cast<const float4*>(x)[(size_t)(rbase + r) * 32 + (i & 31)];
        float* d = &sx[r * TSTRIDE + c4];
        d[0] = v.x; d[1] = v.y; d[2] = v.z; d[3] = v.w;
    }
    __syncthreads();

    float acc[4][8];
#pragma unroll
    for (int i = 0; i < 4; i++)
#pragma unroll
        for (int j = 0; j < 8; j++) acc[i][j] = 0.f;

    for (int k = 0; k < 128; k++) {
        float a[4];
#pragma unroll
        for (int i = 0; i < 4; i++) a[i] = sx[(r0 + i) * TSTRIDE + k];
        float4 w0 = *reinterpret_cast<const float4*>(&sW[k * 128 + c0]);
        float4 w1 = *reinterpret_cast<const float4*>(&sW[k * 128 + c0 + 4]);
        float w[8] = {w0.x, w0.y, w0.z, w0.w, w1.x, w1.y, w1.z, w1.w};
#pragma unroll
        for (int i = 0; i < 4; i++)
#pragma unroll
            for (int j = 0; j < 8; j++) acc[i][j] = fmaf(a[i], w[j], acc[i][j]);
    }

#pragma unroll
    for (int i = 0; i < 4; i++) {
        int r = rbase + r0 + i;
        if (r < N_ATOMS) {
            float4 o0 = make_float4(acc[i][0], acc[i][1], acc[i][2], acc[i][3]);
            float4 o1 = make_float4(acc[i][4], acc[i][5], acc[i][6], acc[i][7]);
            float4* dst = reinterpret_cast<float4*>(&g_h[(size_t)r * 128 + c0]);
            dst[0] = o0; dst[1] = o1;
        }
    }
}

// ---------------------------------------------------------------------------
// Edge kernel: per-tile grid, 2 CTAs/SM, ONE barrier per tile, direct RED
// scatter (no staging buffer).  smem (bytes):
//   0      : B_hi (34816)
//   34816  : B_lo (34816)
//   69632  : f_hi (10240)
//   79872  : f_lo (10240)
//   90112  : W1_hi (10240)
//   100352 : W1_lo (10240)
//   110592 : sb1(512) sb2(512) src(512) sii(512) sjj(512)  -> 113152
// ---------------------------------------------------------------------------
#define OFF_BHI  0
#define OFF_BLO  34816
#define OFF_FH   69632
#define OFF_FL   79872
#define OFF_W1H  90112
#define OFF_W1L  100352
#define OFF_B1   110592
#define OFF_B2   111104
#define OFF_RC   111616
#define OFF_II   112128
#define OFF_JJ   112640
#define SMEM_EDGE 113152

__global__ void __launch_bounds__(256, 2)
edge_kernel(const float* __restrict__ f_ij, const float* __restrict__ rcut,
            const int* __restrict__ idx_i, const int* __restrict__ idx_j,
            const float* __restrict__ b1, const float* __restrict__ b2) {
    extern __shared__ __align__(16) unsigned char smraw[];
    const int tid = threadIdx.x;
    const int wid = tid >> 5, lane = tid & 31;
    const uint32_t sbase = smem_u32(smraw);
    const int ebase = blockIdx.x * 128;

    float* sb1  = (float*)(smraw + OFF_B1);
    float* sb2  = (float*)(smraw + OFF_B2);
    float* src  = (float*)(smraw + OFF_RC);
    int*   sii  = (int*)(smraw + OFF_II);
    int*   sjj  = (int*)(smraw + OFF_JJ);

    // f / rcut / idx LDG into registers (overlaps the B/W1 staging below)
    const int fe = tid >> 1, fk0 = (tid & 1) * 10;
    float2 fv[5];
    {
        const float2* fg = (const float2*)(f_ij + (size_t)ebase * NRBF);
        const int fb = fe * 10 + (fk0 >> 1);
#pragma unroll
        for (int j = 0; j < 5; j++) fv[j] = fg[fb + j];
    }
    float prc = 0.f; int pii = 0, pjj = 0;
    if (tid < 128) {
        prc = rcut[ebase + tid];
        pii = idx_i[ebase + tid];
        pjj = idx_j[ebase + tid];
    }

    // ---- single staging phase: B, W1, f hi/lo (+pad zero), biases, misc
    {
        uint4* d1 = (uint4*)(smraw + OFF_BHI);
        uint4* d2 = (uint4*)(smraw + OFF_BLO);
        const uint4* s1 = (const uint4*)g_Bhi;
        const uint4* s2 = (const uint4*)g_Blo;
        for (int i = tid; i < BTILE_BYTES / 16; i += 256) { d1[i] = s1[i]; d2[i] = s2[i]; }
        uint4* w1 = (uint4*)(smraw + OFF_W1H);
        uint4* w2 = (uint4*)(smraw + OFF_W1L);
        const uint4* t1 = (const uint4*)g_W1h;
        const uint4* t2 = (const uint4*)g_W1l;
        for (int i = tid; i < W1TILE_BYTES / 16; i += 256) { w1[i] = t1[i]; w2[i] = t2[i]; }

        // f convert: cols fk0..fk0+9 of row fe in both buffers
        uint32_t* fh = (uint32_t*)(smraw + OFF_FH);
        uint32_t* fl = (uint32_t*)(smraw + OFF_FL);
        const int base = (fe * (W1STR * 2) + fk0 * 2) >> 2;
#pragma unroll
        for (int j = 0; j < 5; j++) {
            float v0 = fv[j].x, v1 = fv[j].y;
            uint32_t h = pack2bf(v0, v1);
            float e0 = v0 - __uint_as_float(h << 16);
            float e1 = v1 - __uint_as_float(h & 0xFFFF0000u);
            fh[base + j] = h;
            fl[base + j] = pack2bf(e0, e1);
        }
        // zero pad cols 20..31 (bytes 40..63): disjoint from convert writes
        unsigned char* fb = smraw + (tid < 128 ? OFF_FH : OFF_FL) +
                            (uint32_t)(tid & 127) * (W1STR * 2) + 40;
        *(uint2*)(fb)      = make_uint2(0u, 0u);
        *(uint2*)(fb + 8)  = make_uint2(0u, 0u);
        *(uint2*)(fb + 16) = make_uint2(0u, 0u);

        if (tid < 128) {
            sb1[tid] = b1[tid];
            sb2[tid] = b2[tid];
            src[tid] = prc; sii[tid] = pii; sjj[tid] = pjj;
        }
    }
    __syncthreads();   // the ONLY barrier in this kernel

    const int q = lane & 3, gr = lane >> 2;
    const int r0 = wid * 16 + gr, r1 = r0 + 8;
    const int koff = (lane >> 4) << 3;
    const int nlo = lane & 15;

    // ---- GEMM1 on tensor cores: t = ssp(f @ W1 + b1) -> A fragments
    uint32_t a_hi[8][4], a_lo[8][4];
    {
        float acc1[16][4];
#pragma unroll
        for (int t = 0; t < 16; t++)
#pragma unroll
            for (int j = 0; j < 4; j++) acc1[t][j] = 0.f;

        const uint32_t afh = sbase + OFF_FH + (uint32_t)(wid * 16 + nlo) * (W1STR * 2);
        const uint32_t afl = sbase + OFF_FL + (uint32_t)(wid * 16 + nlo) * (W1STR * 2);
#pragma unroll
        for (int kk = 0; kk < 2; kk++) {
            const uint32_t kb = (uint32_t)(kk * 16 + koff) * 2;
            uint32_t fh4[4], fl4[4];
            ldsm_x4(afh + kb, fh4);
            ldsm_x4(afl + kb, fl4);
#pragma unroll
            for (int ntp = 0; ntp < 8; ntp++) {
                const uint32_t baddr = (uint32_t)(ntp * 16 + nlo) * (W1STR * 2) + kb;
                uint32_t wh[4], wl[4];
                ldsm_x4(sbase + OFF_W1H + baddr, wh);
                ldsm_x4(sbase + OFF_W1L + baddr, wl);
                mma_bf16(acc1[2 * ntp],     fh4, wh[0], wh[2]);
                mma_bf16(acc1[2 * ntp + 1], fh4, wh[1], wh[3]);
                mma_bf16(acc1[2 * ntp],     fh4, wl[0], wl[2]);
                mma_bf16(acc1[2 * ntp + 1], fh4, wl[1], wl[3]);
                mma_bf16(acc1[2 * ntp],     fl4, wh[0], wh[2]);
                mma_bf16(acc1[2 * ntp + 1], fl4, wh[1], wh[3]);
            }
        }

#pragma unroll
        for (int n = 0; n < 16; n++) {
            const int c0 = 8 * n + 2 * q;
            float2 bv = *(const float2*)(sb1 + c0);
            float t00 = sspf(acc1[n][0] + bv.x);
            float t01 = sspf(acc1[n][1] + bv.y);
            float t10 = sspf(acc1[n][2] + bv.x);
            float t11 = sspf(acc1[n][3] + bv.y);
            uint32_t h0 = pack2bf(t00, t01);
            uint32_t h1 = pack2bf(t10, t11);
            float e00 = t00 - __uint_as_float(h0 << 16);
            float e01 = t01 - __uint_as_float(h0 & 0xFFFF0000u);
            float e10 = t10 - __uint_as_float(h1 << 16);
            float e11 = t11 - __uint_as_float(h1 & 0xFFFF0000u);
            const int kk = n >> 1, hf = (n & 1) * 2;
            a_hi[kk][hf] = h0; a_hi[kk][hf + 1] = h1;
            a_lo[kk][hf] = pack2bf(e00, e01);
            a_lo[kk][hf + 1] = pack2bf(e10, e11);
        }
    }

    // per-tile epilogue constants
    const float rc0 = src[r0], rc1 = src[r1];
    const int   ii0 = sii[r0], ii1 = sii[r1];
    const int   j0 = sjj[r0],  j1 = sjj[r1];
    const float2* const h0p = (const float2*)(g_h + (size_t)j0 * 128);
    const float2* const h1p = (const float2*)(g_h + (size_t)j1 * 128);
    float* const y0base = g_y + (size_t)ii0 * 128;
    float* const y1base = g_y + (size_t)ii1 * 128;
    const bool same_atom = (ii0 == ii1);

    // ---- 4 column-quarter passes of GEMM2 + direct RED scatter (no syncs)
#pragma unroll
    for (int p = 0; p < 4; p++) {
        const int colbase = p * 32;

        float acc[4][4];
#pragma unroll
        for (int t = 0; t < 4; t++)
#pragma unroll
            for (int j = 0; j < 4; j++) acc[t][j] = 0.f;

#pragma unroll
        for (int kk = 0; kk < 8; kk++) {
            const uint32_t kb = (uint32_t)(kk * 16 + koff) * 2;
#pragma unroll
            for (int np = 0; np < 2; np++) {
                const int nrow = colbase + np * 16 + nlo;
                const uint32_t baddr = (uint32_t)nrow * (KSTR * 2) + kb;
                uint32_t bh[4], bl[4];
                ldsm_x4(sbase + OFF_BHI + baddr, bh);
                ldsm_x4(sbase + OFF_BLO + baddr, bl);
                mma_bf16(acc[2 * np],     a_hi[kk], bh[0], bh[2]);
                mma_bf16(acc[2 * np + 1], a_hi[kk], bh[1], bh[3]);
                mma_bf16(acc[2 * np],     a_hi[kk], bl[0], bl[2]);
                mma_bf16(acc[2 * np + 1], a_hi[kk], bl[1], bl[3]);
                mma_bf16(acc[2 * np],     a_lo[kk], bh[0], bh[2]);
                mma_bf16(acc[2 * np + 1], a_lo[kk], bh[1], bh[3]);
            }
        }

        // modulate + reduce directly to g_y (L2-side RED, no smem)
#pragma unroll
        for (int nt = 0; nt < 4; nt++) {
            const int c = colbase + 8 * nt + 2 * q;
            float2 bv = *(const float2*)(sb2 + c);
            float2 hv0 = h0p[c >> 1];
            float2 hv1 = h1p[c >> 1];
            float vx0 = (acc[nt][0] + bv.x) * rc0 * hv0.x;
            float vy0 = (acc[nt][1] + bv.y) * rc0 * hv0.y;
            float vx1 = (acc[nt][2] + bv.x) * rc1 * hv1.x;
            float vy1 = (acc[nt][3] + bv.y) * rc1 * hv1.y;
            if (same_atom) {
                red_add_f32x2(y0base + c, vx0 + vx1, vy0 + vy1);
            } else {
                red_add_f32x2(y0base + c, vx0, vy0);
                red_add_f32x2(y1base + c, vx1, vy1);
            }
        }
    }
}

// ---------------------------------------------------------------------------
// out = ssp(y @ W_o1 + b_o1) @ W_o2 + b_o2   (512 threads, 4x8 micro-tile)
// ---------------------------------------------------------------------------
__global__ void __launch_bounds__(512, 1)
out_kernel(const float* __restrict__ Wo1, const float* __restrict__ bo1,
           const float* __restrict__ Wo2, const float* __restrict__ bo2,
           float* __restrict__ out) {
    extern __shared__ float sm[];
    float* sy = sm;
    float* sW = sm + 128 * TSTRIDE;
    float* sb = sW + 16384;

    const int tid = threadIdx.x;
    const int tx = tid & 15, ty = tid >> 4;
    const int c0 = tx * 8, r0 = ty * 4;
    const int rbase = blockIdx.x * 128;

    for (int i = tid; i < 4096; i += 512)
        reinterpret_cast<float4*>(sW)[i] = reinterpret_cast<const float4*>(Wo1)[i];
    if (tid < 128) sb[tid] = bo1[tid];
    for (int i = tid; i < 128 * 32; i += 512) {
        int r = i >> 5, c4 = (i & 31) * 4;
        float4 v = make_float4(0.f, 0.f, 0.f, 0.f);
        if (rbase + r < N_ATOMS)
            v = reinterpret_cast<const float4*>(g_y)[(size_t)(rbase + r) * 32 + (i & 31)];
        float* d = &sy[r * TSTRIDE + c4];
        d[0] = v.x; d[1] = v.y; d[2] = v.z; d[3] = v.w;
    }
    __syncthreads();

    float acc[4][8];
#pragma unroll
    for (int i = 0; i < 4; i++)
#pragma unroll
        for (int j = 0; j < 8; j++) acc[i][j] = 0.f;

    for (int k = 0; k < 128; k++) {
        float a[4];
#pragma unroll
        for (int i = 0; i < 4; i++) a[i] = sy[(r0 + i) * TSTRIDE + k];
        float4 w0 = *reinterpret_cast<const float4*>(&sW[k * 128 + c0]);
        float4 w1 = *reinterpret_cast<const float4*>(&sW[k * 128 + c0 + 4]);
        float w[8] = {w0.x, w0.y, w0.z, w0.w, w1.x, w1.y, w1.z, w1.w};
#pragma unroll
        for (int i = 0; i < 4; i++)
#pragma unroll
            for (int j = 0; j < 8; j++) acc[i][j] = fmaf(a[i], w[j], acc[i][j]);
    }
    __syncthreads();

#pragma unroll
    for (int i = 0; i < 4; i++)
#pragma unroll
        for (int j = 0; j < 8; j++)
            sy[(r0 + i) * TSTRIDE + c0 + j] = sspf(acc[i][j] + sb[c0 + j]);
    __syncthreads();

    for (int i = tid; i < 4096; i += 512)
        reinterpret_cast<float4*>(sW)[i] = reinterpret_cast<const float4*>(Wo2)[i];
    if (tid < 128) sb[tid] = bo2[tid];
    __syncthreads();

    float acc2[4][8];
#pragma unroll
    for (int i = 0; i < 4; i++)
#pragma unroll
        for (int j = 0; j < 8; j++) acc2[i][j] = 0.f;

    for (int k = 0; k < 128; k++) {
        float a[4];
#pragma unroll
        for (int i = 0; i < 4; i++) a[i] = sy[(r0 + i) * TSTRIDE + k];
        float4 w0 = *reinterpret_cast<const float4*>(&sW[k * 128 + c0]);
        float4 w1 = *reinterpret_cast<const float4*>(&sW[k * 128 + c0 + 4]);
        float w[8] = {w0.x, w0.y, w0.z, w0.w, w1.x, w1.y, w1.z, w1.w};
#pragma unroll
        for (int i = 0; i < 4; i++)
#pragma unroll
            for (int j = 0; j < 8; j++) acc2[i][j] = fmaf(a[i], w[j], acc2[i][j]);
    }

#pragma unroll
    for (int i = 0; i < 4; i++) {
        int r = rbase + r0 + i;
        if (r < N_ATOMS) {
            float4 o0 = make_float4(acc2[i][0] + sb[c0 + 0], acc2[i][1] + sb[c0 + 1],
                                    acc2[i][2] + sb[c0 + 2], acc2[i][3] + sb[c0 + 3]);
            float4 o1 = make_float4(acc2[i][4] + sb[c0 + 4], acc2[i][5] + sb[c0 + 5],
                                    acc2[i][6] + sb[c0 + 6], acc2[i][7] + sb[c0 + 7]);
            float4* dst = reinterpret_cast<float4*>(&out[(size_t)r * 128 + c0]);
            dst[0] = o0; dst[1] = o1;
        }
    }
}

// ---------------------------------------------------------------------------
extern "C" void kernel_launch(void* const* d_in, const int* in_sizes, int n_in,
                              void* d_out, int out_size) {
    const float* x      = (const float*)d_in[0];
    const float* f_ij   = (const float*)d_in[1];
    const float* rcut   = (const float*)d_in[2];
    const int*   idx_i  = (const int*)d_in[3];
    const int*   idx_j  = (const int*)d_in[4];
    const float* W_in2f = (const float*)d_in[5];
    const float* W_f1   = (const float*)d_in[6];
    const float* b_f1   = (const float*)d_in[7];
    const float* W_f2   = (const float*)d_in[8];
    const float* b_f2   = (const float*)d_in[9];
    const float* W_o1   = (const float*)d_in[10];
    const float* b_o1   = (const float*)d_in[11];
    const float* W_o2   = (const float*)d_in[12];
    const float* b_o2   = (const float*)d_in[13];
    float* out = (float*)d_out;

    const int smemA = (128 * TSTRIDE + 128 * 128) * 4;
    const int smemC = (128 * TSTRIDE + 128 * 128 + 128) * 4;

    cudaFuncSetAttribute(h_kernel, cudaFuncAttributeMaxDynamicSharedMemorySize, smemA);
    cudaFuncSetAttribute(edge_kernel, cudaFuncAttributeMaxDynamicSharedMemorySize, SMEM_EDGE);
    cudaFuncSetAttribute(out_kernel, cudaFuncAttributeMaxDynamicSharedMemorySize, smemC);

    prep_w2_kernel<<<64, 256>>>(W_f2);
    prep_w1_kernel<<<20, 256>>>(W_f1);
    h_kernel<<<(N_ATOMS + 127) / 128, 512, smemA>>>(x, W_in2f);
    edge_kernel<<<NTILES, 256, SMEM_EDGE>>>(f_ij, rcut, idx_i, idx_j,
                                            b_f1, b_f2);
    out_kernel<<<(N_ATOMS + 127) / 128, 512, smemC>>>(W_o1, b_o1, W_o2, b_o2, out);
}